// round 4
// baseline (speedup 1.0000x reference)
#include <cuda_runtime.h>
#include <cstdint>

typedef unsigned long long u64;

#define BATCH 32
#define HID   64
#define CHUNK 2048
#define CMASK (CHUNK-1)
#define LOGC  11

__device__ __forceinline__ u64 fma2(u64 a, u64 b, u64 c){
    u64 d; asm("fma.rn.f32x2 %0, %1, %2, %3;" : "=l"(d) : "l"(a), "l"(b), "l"(c)); return d;
}
__device__ __forceinline__ u64 add2(u64 a, u64 b){
    u64 d; asm("add.rn.f32x2 %0, %1, %2;" : "=l"(d) : "l"(a), "l"(b)); return d;
}
__device__ __forceinline__ float hsum2(u64 a){
    float lo, hi; asm("mov.b64 {%0,%1}, %2;" : "=f"(lo), "=f"(hi) : "l"(a)); return lo + hi;
}
__device__ __forceinline__ float fsig(float v){       // rel err ~1e-7
    float e = __expf(-v);
    return __fdividef(1.0f, 1.0f + e);
}
__device__ __forceinline__ float ftanh(float v){
    float e = __expf(2.0f * v);
    return 1.0f - __fdividef(2.0f, e + 1.0f);
}

// One CTA = 128 threads = 2 batches via per-thread ILP. Pair (2i,2i+1) owns
// hidden unit i for BOTH batches. Lane p=0: full r-dot; p=1: full z-dot;
// both lanes: half n-dot (combined via shfl_xor 1). The two batches' chains
// are independent within each thread -> static interleave hides MUFU/LDS/SHFL
// latency without any cross-warp arbitration. One __syncthreads covers both.
__global__ void __launch_bounds__(128, 1)
gru_kernel(const float* __restrict__ x, const float* __restrict__ w_ih,
           const float* __restrict__ w_hh, const float* __restrict__ b_ih,
           const float* __restrict__ b_hh, float* __restrict__ states, int T)
{
    __shared__ __align__(16) float hbuf[2][2][HID];   // [buf][batch][unit]
    __shared__ __align__(16) float xs[2][2][CHUNK];   // [batch][buf][t]

    const int tid = threadIdx.x;
    const int i   = tid >> 1;
    const int p   = tid & 1;
    const int ia  = i + 64 * p;        // r-row (p=0) or z-row (p=1)
    const int in_ = 128 + i;           // n-row
    const int bA  = blockIdx.x * 2;
    const int bB  = bA + 1;

    // weights (shared across both batches)
    u64 wa[32];
    {
        const u64* was = (const u64*)(w_hh + ia * 64);
        #pragma unroll
        for (int q = 0; q < 32; q++) wa[q] = was[q];
    }
    u64 wn[16];
    {
        const u64* wns = (const u64*)(w_hh + in_ * 64 + 32 * p);
        #pragma unroll
        for (int q = 0; q < 16; q++) wn[q] = wns[q];
    }

    const float bhh_n = b_hh[in_], bih_n = b_ih[in_], wih_n = w_ih[in_];
    const float wih_a = w_ih[ia];
    const float ca = b_hh[ia] + b_ih[ia];

    const float* xrowA = x + (size_t)bA * T;
    const float* xrowB = x + (size_t)bB * T;

    if (tid < HID) { hbuf[0][0][tid] = 0.0f; hbuf[0][1][tid] = 0.0f; }
    {
        const float4* sA = (const float4*)xrowA;
        const float4* sB = (const float4*)xrowB;
        float4* dA = (float4*)xs[0][0];
        float4* dB = (float4*)xs[1][0];
        #pragma unroll
        for (int q = 0; q < CHUNK / 4 / 128; q++) {
            dA[tid + q * 128] = sA[tid + q * 128];
            dB[tid + q * 128] = sB[tid + q * 128];
        }
    }
    __syncthreads();

    float* soutA = states + ((size_t)bA * T) * HID + i;
    float* soutB = states + ((size_t)bB * T) * HID + i;

    for (int t = 0; t < T; ++t) {
        if ((t & CMASK) == 0) {
            int nc = (t >> LOGC) + 1;
            if (nc * CHUNK < T) {
                const float4* sA = (const float4*)(xrowA + (size_t)nc * CHUNK);
                const float4* sB = (const float4*)(xrowB + (size_t)nc * CHUNK);
                float4* dA = (float4*)xs[0][nc & 1];
                float4* dB = (float4*)xs[1][nc & 1];
                #pragma unroll
                for (int q = 0; q < CHUNK / 4 / 128; q++) {
                    dA[tid + q * 128] = sA[tid + q * 128];
                    dB[tid + q * 128] = sB[tid + q * 128];
                }
            }
        }

        const int cur = t & 1;
        const int xb  = (t >> LOGC) & 1;
        const float* hcA = hbuf[cur][0];
        const float* hcB = hbuf[cur][1];
        const float xtA = xs[0][xb][t & CMASK];
        const float xtB = xs[1][xb][t & CMASK];
        const float hprevA = hcA[i];
        const float hprevB = hcB[i];
        const float xaA = fmaf(xtA, wih_a, ca);
        const float xaB = fmaf(xtB, wih_a, ca);
        const float xnA = fmaf(xtA, wih_n, bih_n);
        const float xnB = fmaf(xtB, wih_n, bih_n);

        // ---- a-dot (r or z), batch A ----
        u64 a0=0,a1=0,a2=0,a3=0,a4=0,a5=0,a6=0,a7=0;
        {
            const ulonglong2* hs = (const ulonglong2*)hcA;
            #pragma unroll
            for (int q = 0; q < 4; q++) {
                ulonglong2 h0 = hs[4*q], h1 = hs[4*q+1], h2 = hs[4*q+2], h3 = hs[4*q+3];
                a0 = fma2(h0.x, wa[8*q],   a0);  a1 = fma2(h0.y, wa[8*q+1], a1);
                a2 = fma2(h1.x, wa[8*q+2], a2);  a3 = fma2(h1.y, wa[8*q+3], a3);
                a4 = fma2(h2.x, wa[8*q+4], a4);  a5 = fma2(h2.y, wa[8*q+5], a5);
                a6 = fma2(h3.x, wa[8*q+6], a6);  a7 = fma2(h3.y, wa[8*q+7], a7);
            }
        }
        float saA = hsum2(add2(add2(add2(a0,a1),add2(a2,a3)),
                               add2(add2(a4,a5),add2(a6,a7))));
        float gaA = fsig(saA + xaA);     // MUFU chain starts; B-dot fills the stall

        // ---- a-dot, batch B ----
        u64 b0=0,b1=0,b2=0,b3=0,b4=0,b5=0,b6=0,b7=0;
        {
            const ulonglong2* hs = (const ulonglong2*)hcB;
            #pragma unroll
            for (int q = 0; q < 4; q++) {
                ulonglong2 h0 = hs[4*q], h1 = hs[4*q+1], h2 = hs[4*q+2], h3 = hs[4*q+3];
                b0 = fma2(h0.x, wa[8*q],   b0);  b1 = fma2(h0.y, wa[8*q+1], b1);
                b2 = fma2(h1.x, wa[8*q+2], b2);  b3 = fma2(h1.y, wa[8*q+3], b3);
                b4 = fma2(h2.x, wa[8*q+4], b4);  b5 = fma2(h2.y, wa[8*q+5], b5);
                b6 = fma2(h3.x, wa[8*q+6], b6);  b7 = fma2(h3.y, wa[8*q+7], b7);
            }
        }
        float saB = hsum2(add2(add2(add2(b0,b1),add2(b2,b3)),
                               add2(add2(b4,b5),add2(b6,b7))));
        float gaB = fsig(saB + xaB);

        // ---- n half-dots (32 floats = 16 u64 each) ----
        u64 nA0=0,nA1=0,nA2=0,nA3=0, nB0=0,nB1=0,nB2=0,nB3=0;
        {
            const ulonglong2* hsA = (const ulonglong2*)(hcA + 32 * p);
            const ulonglong2* hsB = (const ulonglong2*)(hcB + 32 * p);
            #pragma unroll
            for (int q = 0; q < 4; q++) {
                ulonglong2 hA0 = hsA[2*q], hA1 = hsA[2*q+1];
                ulonglong2 hB0 = hsB[2*q], hB1 = hsB[2*q+1];
                nA0 = fma2(hA0.x, wn[4*q],   nA0);  nA1 = fma2(hA0.y, wn[4*q+1], nA1);
                nA2 = fma2(hA1.x, wn[4*q+2], nA2);  nA3 = fma2(hA1.y, wn[4*q+3], nA3);
                nB0 = fma2(hB0.x, wn[4*q],   nB0);  nB1 = fma2(hB0.y, wn[4*q+1], nB1);
                nB2 = fma2(hB1.x, wn[4*q+2], nB2);  nB3 = fma2(hB1.y, wn[4*q+3], nB3);
            }
        }
        float snpA = hsum2(add2(add2(nA0,nA1),add2(nA2,nA3)));
        float snpB = hsum2(add2(add2(nB0,nB1),add2(nB2,nB3)));

        float snA = snpA + __shfl_xor_sync(0xffffffffu, snpA, 1);
        float snB = snpB + __shfl_xor_sync(0xffffffffu, snpB, 1);
        float gbA = __shfl_xor_sync(0xffffffffu, gaA, 1);
        float gbB = __shfl_xor_sync(0xffffffffu, gaB, 1);

        float rA = p ? gbA : gaA,  zA = p ? gaA : gbA;
        float rB = p ? gbB : gaB,  zB = p ? gaB : gbB;

        float nvA = ftanh(fmaf(rA, snA + bhh_n, xnA));
        float nvB = ftanh(fmaf(rB, snB + bhh_n, xnB));
        float hnewA = fmaf(zA, hprevA - nvA, nvA);
        float hnewB = fmaf(zB, hprevB - nvB, nvB);

        if (!p) {
            hbuf[cur ^ 1][0][i] = hnewA;
            hbuf[cur ^ 1][1][i] = hnewB;
            soutA[(size_t)t * HID] = hnewA;
            soutB[(size_t)t * HID] = hnewB;
        }
        __syncthreads();
    }
}

// out[n] = dot(states[n,:], w_lin) + b_lin + x[n]
#define HROWS 128
#define HPAD  65
__global__ void __launch_bounds__(128, 4)
head_kernel(const float* __restrict__ st, const float* __restrict__ x,
            const float* __restrict__ wl, const float* __restrict__ bl,
            float* __restrict__ out, int BT)
{
    __shared__ float tile[HROWS * HPAD];
    __shared__ float wsh[HID];

    const int tid = threadIdx.x;
    const size_t row0 = (size_t)blockIdx.x * HROWS;

    if (tid < HID) wsh[tid] = wl[tid];

    const float4* src = (const float4*)(st + row0 * HID);
    #pragma unroll
    for (int q = 0; q < (HROWS * HID / 4) / 128; q++) {
        int f4 = tid + q * 128;
        float4 v = src[f4];
        int flat = f4 * 4;
        int r = flat >> 6;
        int c = flat & 63;
        float* drow = &tile[r * HPAD + c];
        drow[0] = v.x; drow[1] = v.y; drow[2] = v.z; drow[3] = v.w;
    }
    __syncthreads();

    const float* trow = &tile[tid * HPAD];
    float acc = 0.0f;
    #pragma unroll
    for (int k = 0; k < HID; k++) acc = fmaf(trow[k], wsh[k], acc);

    size_t n = row0 + tid;
    out[n] = acc + bl[0] + x[n];
}

extern "C" void kernel_launch(void* const* d_in, const int* in_sizes, int n_in,
                              void* d_out, int out_size)
{
    const float* x     = (const float*)d_in[0];
    const float* w_ih  = (const float*)d_in[1];
    const float* w_hh  = (const float*)d_in[2];
    const float* b_ih  = (const float*)d_in[3];
    const float* b_hh  = (const float*)d_in[4];
    const float* w_lin = (const float*)d_in[5];
    const float* b_lin = (const float*)d_in[6];

    float* out = (float*)d_out;
    const int BT = in_sizes[0];          // B * T
    const int T  = BT / BATCH;
    float* states = out + BT;            // d_out = [out | states]

    gru_kernel<<<BATCH / 2, 128>>>(x, w_ih, w_hh, b_ih, b_hh, states, T);
    head_kernel<<<BT / HROWS, 128>>>(states, x, w_lin, b_lin, out, BT);
}

// round 5
// speedup vs baseline: 1.7749x; 1.7749x over previous
#include <cuda_runtime.h>
#include <cstdint>

typedef unsigned long long u64;

#define BATCH 32
#define HID   64
#define CHUNK 2048
#define LOGC  11

__device__ __forceinline__ u64 fma2(u64 a, u64 b, u64 c){
    u64 d; asm("fma.rn.f32x2 %0, %1, %2, %3;" : "=l"(d) : "l"(a), "l"(b), "l"(c)); return d;
}
__device__ __forceinline__ u64 add2(u64 a, u64 b){
    u64 d; asm("add.rn.f32x2 %0, %1, %2;" : "=l"(d) : "l"(a), "l"(b)); return d;
}
__device__ __forceinline__ float hsum2(u64 a){
    float lo, hi; asm("mov.b64 {%0,%1}, %2;" : "=f"(lo), "=f"(hi) : "l"(a)); return lo + hi;
}
__device__ __forceinline__ float fsig(float v){       // rel err ~1e-7
    float e = __expf(-v);
    return __fdividef(1.0f, 1.0f + e);
}
__device__ __forceinline__ float ftanh(float v){
    float e = __expf(2.0f * v);
    return 1.0f - __fdividef(2.0f, e + 1.0f);
}

// One CTA per batch row (32 CTAs, each alone on an SM). 128 threads; pair
// (2i,2i+1) owns hidden unit i. Lane p=0: full 64-dot for r; p=1: full 64-dot
// for z; both lanes: half 32-dot for n (combined via shfl_xor 1).
// Branch-free inner loop: outer loop over x chunks (prefetch hoisted),
// manual unroll x2 with explicit hbuf ping-pong, hprev kept in register.
__global__ void __launch_bounds__(128, 1)
gru_kernel(const float* __restrict__ x, const float* __restrict__ w_ih,
           const float* __restrict__ w_hh, const float* __restrict__ b_ih,
           const float* __restrict__ b_hh, float* __restrict__ states, int T)
{
    __shared__ __align__(16) float hbuf[2][HID];
    __shared__ __align__(16) float xs[2][CHUNK];

    const int tid = threadIdx.x;
    const int b   = blockIdx.x;
    const int i   = tid >> 1;
    const int p   = tid & 1;
    const int ia  = i + 64 * p;        // r-row (p=0) or z-row (p=1)
    const int in_ = 128 + i;           // n-row

    // weights into registers (packed f32x2)
    u64 wa[32];
    {
        const u64* was = (const u64*)(w_hh + ia * 64);
        #pragma unroll
        for (int q = 0; q < 32; q++) wa[q] = was[q];
    }
    u64 wn[16];
    {
        const u64* wns = (const u64*)(w_hh + in_ * 64 + 32 * p);
        #pragma unroll
        for (int q = 0; q < 16; q++) wn[q] = wns[q];
    }

    const float bhh_n = b_hh[in_], bih_n = b_ih[in_], wih_n = w_ih[in_];
    const float wih_a = w_ih[ia];
    const float ca = b_hh[ia] + b_ih[ia];

    const float* xrow = x + (size_t)b * T;

    if (tid < HID) hbuf[0][tid] = 0.0f;
    {
        const float4* src = (const float4*)xrow;
        float4* dst = (float4*)xs[0];
        #pragma unroll
        for (int q = 0; q < CHUNK / 4 / 128; q++) dst[tid + q * 128] = src[tid + q * 128];
    }
    __syncthreads();

    float* sout = states + ((size_t)b * T) * HID + i;
    float hprev = 0.0f;
    const int nch = T >> LOGC;

    // one GRU step: read h from HC, write new h to HD
    auto step = [&](const float* hc, float* hd, float xt, float* sp) {
        const float xa  = fmaf(xt, wih_a, ca);
        const float xn_ = fmaf(xt, wih_n, bih_n);

        // full 64-dot for gate a (r or z): 8 accumulators
        u64 a0=0,a1=0,a2=0,a3=0,a4=0,a5=0,a6=0,a7=0;
        const ulonglong2* hs = (const ulonglong2*)hc;
        #pragma unroll
        for (int q = 0; q < 4; q++) {
            ulonglong2 h0 = hs[4*q], h1 = hs[4*q+1], h2 = hs[4*q+2], h3 = hs[4*q+3];
            a0 = fma2(h0.x, wa[8*q],   a0);  a1 = fma2(h0.y, wa[8*q+1], a1);
            a2 = fma2(h1.x, wa[8*q+2], a2);  a3 = fma2(h1.y, wa[8*q+3], a3);
            a4 = fma2(h2.x, wa[8*q+4], a4);  a5 = fma2(h2.y, wa[8*q+5], a5);
            a6 = fma2(h3.x, wa[8*q+6], a6);  a7 = fma2(h3.y, wa[8*q+7], a7);
        }
        float sa = hsum2(add2(add2(add2(a0,a1),add2(a2,a3)),
                              add2(add2(a4,a5),add2(a6,a7))));
        float ga = fsig(sa + xa);          // MUFU chain overlaps n-dot below

        // half 32-dot for n-gate (16 u64 = 32 floats)
        u64 n0=0,n1=0,n2=0,n3=0;
        const ulonglong2* hsn = (const ulonglong2*)(hc + 32 * p);
        #pragma unroll
        for (int q = 0; q < 4; q++) {
            ulonglong2 h0 = hsn[2*q], h1 = hsn[2*q+1];
            n0 = fma2(h0.x, wn[4*q],   n0);  n1 = fma2(h0.y, wn[4*q+1], n1);
            n2 = fma2(h1.x, wn[4*q+2], n2);  n3 = fma2(h1.y, wn[4*q+3], n3);
        }
        float snp = hsum2(add2(add2(n0,n1),add2(n2,n3)));
        float sn  = snp + __shfl_xor_sync(0xffffffffu, snp, 1);
        float gb  = __shfl_xor_sync(0xffffffffu, ga, 1);
        float r = p ? gb : ga;
        float z = p ? ga : gb;
        float nv = ftanh(fmaf(r, sn + bhh_n, xn_));
        float hnew = fmaf(z, hprev - nv, nv);   // (1-z)*n + z*h
        hprev = hnew;

        if (!p) {
            hd[i] = hnew;
            __stcs(sp, hnew);                   // streaming store of states
        }
        __syncthreads();
    };

    for (int c = 0; c < nch; c++) {
        // prefetch next chunk (outside the hot loop: one branch per 2048 steps)
        if (c + 1 < nch) {
            const float4* src = (const float4*)(xrow + (size_t)(c + 1) * CHUNK);
            float4* dst = (float4*)xs[(c + 1) & 1];
            #pragma unroll
            for (int q = 0; q < CHUNK / 4 / 128; q++) dst[tid + q * 128] = src[tid + q * 128];
        }
        const float* xc = xs[c & 1];
        float* sc = sout + (size_t)c * CHUNK * HID;

        for (int tl = 0; tl < CHUNK; tl += 2) {
            step(hbuf[0], hbuf[1], xc[tl],     sc + (size_t)tl * HID);
            step(hbuf[1], hbuf[0], xc[tl + 1], sc + (size_t)(tl + 1) * HID);
        }
    }
}

// out[n] = dot(states[n,:], w_lin) + b_lin + x[n]
#define HROWS 128
#define HPAD  65
__global__ void __launch_bounds__(128, 4)
head_kernel(const float* __restrict__ st, const float* __restrict__ x,
            const float* __restrict__ wl, const float* __restrict__ bl,
            float* __restrict__ out, int BT)
{
    __shared__ float tile[HROWS * HPAD];
    __shared__ float wsh[HID];

    const int tid = threadIdx.x;
    const size_t row0 = (size_t)blockIdx.x * HROWS;

    if (tid < HID) wsh[tid] = wl[tid];

    const float4* src = (const float4*)(st + row0 * HID);
    #pragma unroll
    for (int q = 0; q < (HROWS * HID / 4) / 128; q++) {
        int f4 = tid + q * 128;
        float4 v = src[f4];
        int flat = f4 * 4;
        int r = flat >> 6;
        int c = flat & 63;
        float* drow = &tile[r * HPAD + c];
        drow[0] = v.x; drow[1] = v.y; drow[2] = v.z; drow[3] = v.w;
    }
    __syncthreads();

    const float* trow = &tile[tid * HPAD];
    float acc = 0.0f;
    #pragma unroll
    for (int k = 0; k < HID; k++) acc = fmaf(trow[k], wsh[k], acc);

    size_t n = row0 + tid;
    out[n] = acc + bl[0] + x[n];
}

extern "C" void kernel_launch(void* const* d_in, const int* in_sizes, int n_in,
                              void* d_out, int out_size)
{
    const float* x     = (const float*)d_in[0];
    const float* w_ih  = (const float*)d_in[1];
    const float* w_hh  = (const float*)d_in[2];
    const float* b_ih  = (const float*)d_in[3];
    const float* b_hh  = (const float*)d_in[4];
    const float* w_lin = (const float*)d_in[5];
    const float* b_lin = (const float*)d_in[6];

    float* out = (float*)d_out;
    const int BT = in_sizes[0];          // B * T
    const int T  = BT / BATCH;
    float* states = out + BT;            // d_out = [out | states]

    gru_kernel<<<BATCH, 128>>>(x, w_ih, w_hh, b_ih, b_hh, states, T);
    head_kernel<<<BT / HROWS, 128>>>(states, x, w_lin, b_lin, out, BT);
}